// round 15
// baseline (speedup 1.0000x reference)
#include <cuda_runtime.h>
#include <cuda_bf16.h>
#include <math.h>
#include <stdint.h>

#define V 50280
#define DM 768
#define NLY 4
#define DS 16
#define DC 4
#define DTR 48
#define ROH 512
#define DI 1536
#define BB 2
#define LL 128
#define BL 256                       // BB*LL
#define DIDS (DI*DS)                 // 24576
#define HID_LAYER_STRIDE (BL*DIDS)   // 6291456

// ---------------- scratch (device globals; no allocation allowed) ----------
__device__ float g_x[BL * DM];
__device__ float g_xz[BL * 2 * DI];
__device__ float g_xconv[BL * DI];
__device__ float g_dbc[BL * 80];
__device__ float g_delta[BL * DI];
__device__ float g_h1[BL * ROH];
// pre-converted bf16 hi/lo activations (GEMM A operands)
__device__ __nv_bfloat16 g_xnh[BL * DM], g_xnl[BL * DM];
__device__ __nv_bfloat16 g_yh[BL * DI], g_yl[BL * DI];
__device__ __nv_bfloat16 g_hidh[NLY * BL * DIDS];
__device__ __nv_bfloat16 g_hidl[NLY * BL * DIDS];
__device__ __nv_bfloat16 g_h2h[BL * 256], g_h2l[BL * 256];

__device__ __forceinline__ void split_bf16(float v, __nv_bfloat16& h, __nv_bfloat16& l) {
    h = __float2bfloat16(v);
    l = __float2bfloat16(v - __bfloat162float(h));
}

// ---------------- embedding gather ----------------
__global__ void k_embed(const int* __restrict__ ids, const float* __restrict__ embed) {
    int i = blockIdx.x * blockDim.x + threadIdx.x;
    if (i < BL * DM) {
        int r = i / DM, c = i % DM;
        g_x[i] = embed[(size_t)ids[r] * DM + c];
    }
}

// ---------------- rmsnorm -> bf16 hi/lo xn ----------------
__global__ void k_rmsnorm(const float* __restrict__ x, const float* __restrict__ w) {
    int r = blockIdx.x;
    int tid = threadIdx.x;
    __shared__ float red[256];
    float s = 0.f;
    for (int c = tid; c < DM; c += 256) {
        float v = x[r * DM + c];
        s += v * v;
    }
    red[tid] = s;
    __syncthreads();
    for (int o = 128; o > 0; o >>= 1) {
        if (tid < o) red[tid] += red[tid + o];
        __syncthreads();
    }
    float scale = rsqrtf(red[0] / DM + 1e-5f);
    for (int c = tid; c < DM; c += 256) {
        float v = x[r * DM + c] * scale * w[c];
        __nv_bfloat16 h, l;
        split_bf16(v, h, l);
        g_xnh[r * DM + c] = h;
        g_xnl[r * DM + c] = l;
    }
}

// ---------------- scalar fp32 GEMM (ro2) -> bf16 hi/lo out ----------------
__global__ void k_gemm_ro2(const float* __restrict__ A, const float* __restrict__ B,
                           const float* __restrict__ bias) {
    __shared__ float As[16][68];
    __shared__ float Bs[16][68];
    int tid = threadIdx.x;
    int bm = blockIdx.y * 64, bn = blockIdx.x * 64;

    float acc[4][4] = {};
    int a_r = tid >> 2, a_k = (tid & 3) * 4;
    int ty = tid >> 4, tx = tid & 15;

    for (int k0 = 0; k0 < ROH; k0 += 16) {
        float4 av = *(const float4*)(A + (size_t)(bm + a_r) * ROH + k0 + a_k);
        As[a_k + 0][a_r] = av.x;
        As[a_k + 1][a_r] = av.y;
        As[a_k + 2][a_r] = av.z;
        As[a_k + 3][a_r] = av.w;
        int b_r = tid >> 4, b_c = (tid & 15) * 4;
        float4 bv = *(const float4*)(B + (size_t)(k0 + b_r) * 256 + bn + b_c);
        *(float4*)&Bs[b_r][b_c] = bv;
        __syncthreads();
#pragma unroll
        for (int kk = 0; kk < 16; kk++) {
            float4 a = *(const float4*)&As[kk][ty * 4];
            float4 b = *(const float4*)&Bs[kk][tx * 4];
            float ar[4] = {a.x, a.y, a.z, a.w};
            float br[4] = {b.x, b.y, b.z, b.w};
#pragma unroll
            for (int i = 0; i < 4; i++)
#pragma unroll
                for (int j = 0; j < 4; j++) acc[i][j] = fmaf(ar[i], br[j], acc[i][j]);
        }
        __syncthreads();
    }
#pragma unroll
    for (int i = 0; i < 4; i++) {
        int m = bm + ty * 4 + i;
#pragma unroll
        for (int j = 0; j < 4; j++) {
            int n = bn + tx * 4 + j;
            float v = fmaxf(acc[i][j] + bias[n], 0.f);
            __nv_bfloat16 h, l;
            split_bf16(v, h, l);
            g_h2h[m * 256 + n] = h;
            g_h2l[m * 256 + n] = l;
        }
    }
}

// ======= tensor-core GEMM: 64x64 tile, 256 thr, BK=32, 4 CTAs/SM ==========
__device__ __forceinline__ uint32_t smem_u32(const void* p) {
    uint32_t a;
    asm("{ .reg .u64 t; cvta.to.shared.u64 t, %1; cvt.u32.u64 %0, t; }" : "=r"(a) : "l"(p));
    return a;
}
__device__ __forceinline__ void mma_bf16(float* c, const uint32_t* a, const uint32_t* b) {
    asm volatile(
        "mma.sync.aligned.m16n8k16.row.col.f32.bf16.bf16.f32 "
        "{%0,%1,%2,%3}, {%4,%5,%6,%7}, {%8,%9}, {%0,%1,%2,%3};\n"
        : "+f"(c[0]), "+f"(c[1]), "+f"(c[2]), "+f"(c[3])
        : "r"(a[0]), "r"(a[1]), "r"(a[2]), "r"(a[3]), "r"(b[0]), "r"(b[1]));
}
__device__ __forceinline__ void ldsm4(uint32_t* r, uint32_t addr) {
    asm volatile("ldmatrix.sync.aligned.m8n8.x4.shared.b16 {%0,%1,%2,%3}, [%4];"
                 : "=r"(r[0]), "=r"(r[1]), "=r"(r[2]), "=r"(r[3]) : "r"(addr));
}

// A given as pre-split bf16 hi/lo arrays.
// BT: B is (N x K) fp32; else B is (K x N) fp32 (transposed while staging).
// FEAT: A arrays indexed as hidden tensor; MODE 0 store / 2 atomicAdd.
template <bool BT, bool FEAT, int MODE, bool NGUARD, bool HASBIAS>
__global__ void __launch_bounds__(256, 4)
k_mma(const __nv_bfloat16* __restrict__ Agh, const __nv_bfloat16* __restrict__ Agl,
      const float* __restrict__ B, float* __restrict__ C, const float* __restrict__ bias,
      int N, int lda, int ldb, int ldc, int kcount) {
    __shared__ __nv_bfloat16 Ah[64][40];
    __shared__ __nv_bfloat16 Al[64][40];
    __shared__ __nv_bfloat16 Bh[64][40];
    __shared__ __nv_bfloat16 Bl[64][40];

    const int tid = threadIdx.x;
    const int lane = tid & 31, warp = tid >> 5;
    const int wm = warp & 3, wn = warp >> 2;     // 4 m-warps (16 rows) x 2 n-warps (32 cols)
    const int bm = blockIdx.y * 64, bn = blockIdx.x * 64;
    const int kbeg = blockIdx.z * kcount;
    const int qrow = lane >> 2, qcol = (lane & 3) * 2;

    const __nv_bfloat16 *Aph, *Apl;
    int alda = lda;
    if (FEAT) {
        int layer = kbeg / DIDS;
        size_t off = (size_t)layer * HID_LAYER_STRIDE + (kbeg % DIDS);
        Aph = Agh + off;
        Apl = Agl + off;
        alda = DIDS;
    } else {
        Aph = Agh + kbeg;
        Apl = Agl + kbeg;
    }
    const float* Bp = BT ? (B + kbeg) : (B + (size_t)kbeg * ldb);

    float acc[4][4] = {};
    const int a_row = (lane & 15);
    const int a_koff = ((lane >> 4) & 1) * 8;
    const int b_rowsel = (lane & 7) + ((lane >> 4) & 1) * 8;
    const int b_koff = ((lane >> 3) & 1) * 8;

    for (int k0 = 0; k0 < kcount; k0 += 32) {
        // ---- stage A: 64x32 pre-split bf16 (pure copy) ----
        {
            int r = tid >> 2, ck = (tid & 3) * 8;   // 8 bf16 = 16B per thread
            size_t g = (size_t)(bm + r) * alda + k0 + ck;
            *(uint4*)&Ah[r][ck] = *(const uint4*)(Aph + g);
            *(uint4*)&Al[r][ck] = *(const uint4*)(Apl + g);
        }
        // ---- stage B: 64x32 fp32 -> hi/lo ----
        if (BT) {
#pragma unroll
            for (int i = 0; i < 2; i++) {
                int id = tid + i * 256;
                int nr = id >> 3, kq = (id & 7) * 4;
                float4 v = make_float4(0.f, 0.f, 0.f, 0.f);
                if (!NGUARD || (bn + nr) < N)
                    v = *(const float4*)(Bp + (size_t)(bn + nr) * ldb + k0 + kq);
                __nv_bfloat16 h0, h1, h2, h3, l0, l1, l2, l3;
                split_bf16(v.x, h0, l0); split_bf16(v.y, h1, l1);
                split_bf16(v.z, h2, l2); split_bf16(v.w, h3, l3);
                *(__nv_bfloat162*)&Bh[nr][kq] = __halves2bfloat162(h0, h1);
                *(__nv_bfloat162*)&Bh[nr][kq + 2] = __halves2bfloat162(h2, h3);
                *(__nv_bfloat162*)&Bl[nr][kq] = __halves2bfloat162(l0, l1);
                *(__nv_bfloat162*)&Bl[nr][kq + 2] = __halves2bfloat162(l2, l3);
            }
        } else {
#pragma unroll
            for (int i = 0; i < 2; i++) {
                int id = tid + i * 256;
                int kr = id >> 4, nq = (id & 15) * 4;
                float fv[4];
                if (!NGUARD || (bn + nq + 3) < N) {
                    float4 v = *(const float4*)(Bp + (size_t)(k0 + kr) * ldb + bn + nq);
                    fv[0] = v.x; fv[1] = v.y; fv[2] = v.z; fv[3] = v.w;
                } else {
#pragma unroll
                    for (int j = 0; j < 4; j++)
                        fv[j] = (bn + nq + j) < N ? Bp[(size_t)(k0 + kr) * ldb + bn + nq + j] : 0.f;
                }
#pragma unroll
                for (int j = 0; j < 4; j++) {
                    __nv_bfloat16 h, l;
                    split_bf16(fv[j], h, l);
                    Bh[nq + j][kr] = h;
                    Bl[nq + j][kr] = l;
                }
            }
        }
        __syncthreads();
        // ---- compute: 2 k16 steps ----
#pragma unroll
        for (int ks = 0; ks < 32; ks += 16) {
            uint32_t ah[4], al[4], bh[2][4], bl[2][4];
            {
                int r0 = wm * 16 + a_row;
                ldsm4(ah, smem_u32(&Ah[r0][ks + a_koff]));
                ldsm4(al, smem_u32(&Al[r0][ks + a_koff]));
            }
#pragma unroll
            for (int np = 0; np < 2; np++) {
                int n0 = wn * 32 + np * 16 + b_rowsel;
                ldsm4(bh[np], smem_u32(&Bh[n0][ks + b_koff]));
                ldsm4(bl[np], smem_u32(&Bl[n0][ks + b_koff]));
            }
#pragma unroll
            for (int np = 0; np < 2; np++)
#pragma unroll
                for (int j = 0; j < 2; j++) {
                    float* c = acc[np * 2 + j];
                    mma_bf16(c, ah, bh[np] + j * 2);
                    mma_bf16(c, al, bh[np] + j * 2);
                    mma_bf16(c, ah, bl[np] + j * 2);
                }
        }
        __syncthreads();
    }

    // ---- epilogue ----
#pragma unroll
    for (int i = 0; i < 2; i++) {
        int m = bm + wm * 16 + qrow + i * 8;
#pragma unroll
        for (int nt = 0; nt < 4; nt++)
#pragma unroll
            for (int j = 0; j < 2; j++) {
                int n = bn + wn * 32 + nt * 8 + qcol + j;
                if (NGUARD && n >= N) continue;
                float v = acc[nt][i * 2 + j];
                if (HASBIAS) v += bias[n];
                size_t idx = (size_t)m * ldc + n;
                if (MODE == 0) C[idx] = v;
                else atomicAdd(&C[idx], v);
            }
    }
}

// ---------------- fused conv+silu, x_proj, dt+softplus (one block per row) --
__global__ void k_cxd(const float* __restrict__ cw, const float* __restrict__ cb,
                      const float* __restrict__ xp, const float* __restrict__ dtw,
                      const float* __restrict__ dtb) {
    int r = blockIdx.x;
    int b = r / LL, t = r % LL;
    int tid = threadIdx.x;
    __shared__ float sxc[DI];
    __shared__ float part[3][80];
    __shared__ float sdbc[80];

    for (int d = tid; d < DI; d += 256) {
        float acc = cb[d];
#pragma unroll
        for (int k = 0; k < DC; k++) {
            int tt = t + k - (DC - 1);
            if (tt >= 0)
                acc = fmaf(cw[d * DC + k], g_xz[(size_t)(b * LL + tt) * (2 * DI) + d], acc);
        }
        acc = acc / (1.f + __expf(-acc));
        sxc[d] = acc;
        g_xconv[r * DI + d] = acc;
    }
    __syncthreads();

    if (tid < 240) {
        int n = tid % 80, ks = tid / 80;
        float acc = 0.f;
        int k0 = ks * 512;
#pragma unroll 8
        for (int k = 0; k < 512; k++) acc = fmaf(sxc[k0 + k], xp[(size_t)(k0 + k) * 80 + n], acc);
        part[ks][n] = acc;
    }
    __syncthreads();
    if (tid < 80) {
        float v = part[0][tid] + part[1][tid] + part[2][tid];
        sdbc[tid] = v;
        g_dbc[r * 80 + tid] = v;
    }
    __syncthreads();

    for (int d = tid; d < DI; d += 256) {
        float a = dtb[d];
#pragma unroll
        for (int k = 0; k < DTR; k++) a = fmaf(sdbc[k], dtw[(size_t)k * DI + d], a);
        g_delta[r * DI + d] = (a > 20.f) ? a : log1pf(__expf(a));
    }
}

// ---------------- scan + gate; emits fp32 hidden + bf16 hi/lo copies --------
__global__ void k_scan(const float* __restrict__ A_log_l, float* __restrict__ hidden,
                       const float* __restrict__ Dp, int layer) {
    int tid = blockIdx.x * blockDim.x + threadIdx.x;  // BB*DI*DS = 49152
    int n = tid & 15;
    int d = (tid >> 4) % DI;
    int b = tid / (DI * DS);
    float Adn = -__expf(A_log_l[d * DS + n]);
    float Dd = Dp[d];
    float h = 0.f;
    size_t lbase = (size_t)layer * HID_LAYER_STRIDE;
    float* hbase = hidden + lbase;
    for (int t = 0; t < LL; t++) {
        int row = b * LL + t;
        float del = g_delta[row * DI + d];
        float u = g_xconv[row * DI + d];
        float Bn = g_dbc[row * 80 + DTR + n];
        float Cn = g_dbc[row * 80 + DTR + DS + n];
        float dA = __expf(del * Adn);
        h = fmaf(dA, h, del * Bn * u);
        size_t idx = (size_t)row * DIDS + d * DS + n;
        hbase[idx] = h;
        __nv_bfloat16 hh, hl;
        split_bf16(h, hh, hl);
        g_hidh[lbase + idx] = hh;
        g_hidl[lbase + idx] = hl;
        float p = h * Cn;
        p += __shfl_xor_sync(0xffffffffu, p, 8, 16);
        p += __shfl_xor_sync(0xffffffffu, p, 4, 16);
        p += __shfl_xor_sync(0xffffffffu, p, 2, 16);
        p += __shfl_xor_sync(0xffffffffu, p, 1, 16);
        if (n == 0) {
            float z = g_xz[(size_t)row * (2 * DI) + DI + d];
            float sz = z / (1.f + __expf(-z));
            float yv = (p + Dd * u) * sz;
            __nv_bfloat16 yh, yl;
            split_bf16(yv, yh, yl);
            g_yh[row * DI + d] = yh;
            g_yl[row * DI + d] = yl;
        }
    }
}

__global__ void k_zero(float* __restrict__ p, int nelem) {
    int i = blockIdx.x * blockDim.x + threadIdx.x;
    if (i < nelem) p[i] = 0.f;
}

__global__ void k_bias_relu(float* __restrict__ p, const float* __restrict__ b, int cols,
                            int nelem) {
    int i = blockIdx.x * blockDim.x + threadIdx.x;
    if (i < nelem) {
        float v = p[i] + b[i % cols];
        p[i] = fmaxf(v, 0.f);
    }
}

// ---------------- launch ----------------
extern "C" void kernel_launch(void* const* d_in, const int* in_sizes, int n_in,
                              void* d_out, int out_size) {
    const int* ids = (const int*)d_in[0];
    const float* embed = (const float*)d_in[1];
    const float* norm_f = (const float*)d_in[2];
    const float* norm_w = (const float*)d_in[3];
    const float* in_proj = (const float*)d_in[4];
    const float* conv_w = (const float*)d_in[5];
    const float* conv_b = (const float*)d_in[6];
    const float* x_proj = (const float*)d_in[7];
    const float* dt_w = (const float*)d_in[8];
    const float* dt_b = (const float*)d_in[9];
    const float* A_log = (const float*)d_in[10];
    const float* Dp = (const float*)d_in[11];
    const float* out_proj = (const float*)d_in[12];
    const float* ro_w1 = (const float*)d_in[13];
    const float* ro_b1 = (const float*)d_in[14];
    const float* ro_w2 = (const float*)d_in[15];
    const float* ro_b2 = (const float*)d_in[16];
    const float* ro_w3 = (const float*)d_in[17];
    const float* ro_b3 = (const float*)d_in[18];
    (void)in_sizes; (void)n_in; (void)out_size;

    float* out = (float*)d_out;
    float* out_main = out;                            // (B,L,V)
    float* out_ro = out + (size_t)BL * V;             // (B,L,V)
    float* out_hid = out + (size_t)2 * BL * V;        // (NL,B,L,DI,DS)

    float *x, *xz, *h1;
    __nv_bfloat16 *xnh, *xnl, *yh, *yl, *hidh, *hidl, *h2h, *h2l;
    cudaGetSymbolAddress((void**)&x, g_x);
    cudaGetSymbolAddress((void**)&xz, g_xz);
    cudaGetSymbolAddress((void**)&h1, g_h1);
    cudaGetSymbolAddress((void**)&xnh, g_xnh);
    cudaGetSymbolAddress((void**)&xnl, g_xnl);
    cudaGetSymbolAddress((void**)&yh, g_yh);
    cudaGetSymbolAddress((void**)&yl, g_yl);
    cudaGetSymbolAddress((void**)&hidh, g_hidh);
    cudaGetSymbolAddress((void**)&hidl, g_hidl);
    cudaGetSymbolAddress((void**)&h2h, g_h2h);
    cudaGetSymbolAddress((void**)&h2l, g_h2l);

    k_embed<<<(BL * DM + 255) / 256, 256>>>(ids, embed);

    for (int l = 0; l < NLY; l++) {
        k_rmsnorm<<<BL, 256>>>(x, norm_w + (size_t)l * DM);

        // xz = xn @ in_proj[l]  split-K z=2 -> 384 CTAs
        k_zero<<<(BL * 2 * DI + 255) / 256, 256>>>(xz, BL * 2 * DI);
        k_mma<false, false, 2, false, false><<<dim3(2 * DI / 64, BL / 64, 2), 256>>>(
            xnh, xnl, in_proj + (size_t)l * DM * 2 * DI, xz, nullptr, 2 * DI, DM, 2 * DI,
            2 * DI, DM / 2);

        // fused conv+silu, x_proj, dt+softplus
        k_cxd<<<BL, 256>>>(conv_w + (size_t)l * DI * DC, conv_b + (size_t)l * DI,
                           x_proj + (size_t)l * DI * 80, dt_w + (size_t)l * DTR * DI,
                           dt_b + (size_t)l * DI);

        // scan + gate (emits hidden fp32 + bf16 hi/lo, y bf16 hi/lo)
        k_scan<<<(BB * DI * DS) / 256, 256>>>(A_log + (size_t)l * DIDS, out_hid,
                                              Dp + (size_t)l * DI, l);

        // x += y @ out_proj[l]  split-K z=4 -> 192 CTAs, atomic into residual x
        k_mma<false, false, 2, false, false><<<dim3(DM / 64, BL / 64, 4), 256>>>(
            yh, yl, out_proj + (size_t)l * DI * DM, x, nullptr, DM, DI, DM, DM, DI / 4);
    }

    // final norm + tied lm head: main_logits = xn @ embed^T
    k_rmsnorm<<<BL, 256>>>(x, norm_f);
    k_mma<true, false, 0, true, false><<<dim3((V + 63) / 64, BL / 64, 1), 256>>>(
        xnh, xnl, embed, out_main, nullptr, V, DM, DM, V, DM);

    // readout layer 1: h1 = relu(feat @ ro_w1 + b1), split-K 16x6144 -> 512 CTAs
    k_zero<<<(BL * ROH + 255) / 256, 256>>>(h1, BL * ROH);
    k_mma<false, true, 2, false, false><<<dim3(ROH / 64, BL / 64, 16), 256>>>(
        hidh, hidl, ro_w1, h1, nullptr, ROH, 0, ROH, ROH, (NLY * DIDS) / 16);
    k_bias_relu<<<(BL * ROH + 255) / 256, 256>>>(h1, ro_b1, ROH, BL * ROH);

    // readout layer 2: h2 = relu(h1 @ ro_w2 + b2) -> bf16 hi/lo
    k_gemm_ro2<<<dim3(256 / 64, BL / 64), 256>>>(h1, ro_w2, ro_b2);

    // readout logits = h2 @ ro_w3 + b3
    k_mma<false, false, 0, true, true><<<dim3((V + 63) / 64, BL / 64, 1), 256>>>(
        h2h, h2l, ro_w3, out_ro, ro_b3, V, 256, V, V, 256);
}

// round 16
// speedup vs baseline: 1.3649x; 1.3649x over previous
#include <cuda_runtime.h>
#include <cuda_bf16.h>
#include <math.h>
#include <stdint.h>

#define V 50280
#define DM 768
#define NLY 4
#define DS 16
#define DC 4
#define DTR 48
#define ROH 512
#define DI 1536
#define BB 2
#define LL 128
#define BL 256                       // BB*LL
#define DIDS (DI*DS)                 // 24576
#define HID_LAYER_STRIDE (BL*DIDS)   // 6291456

// ---------------- scratch (device globals; no allocation allowed) ----------
__device__ float g_x[BL * DM];
__device__ float g_xn[BL * DM];
__device__ float g_xz[BL * 2 * DI];
__device__ float g_xconv[BL * DI];
__device__ float g_dbc[BL * 80];
__device__ float g_delta[BL * DI];
__device__ float g_y[BL * DI];
__device__ float g_h1[BL * ROH];
__device__ float g_h2[BL * 256];

// ---------------- embedding gather ----------------
__global__ void k_embed(const int* __restrict__ ids, const float* __restrict__ embed) {
    int i = blockIdx.x * blockDim.x + threadIdx.x;
    if (i < BL * DM) {
        int r = i / DM, c = i % DM;
        g_x[i] = embed[(size_t)ids[r] * DM + c];
    }
}

// ---------------- rmsnorm ----------------
__global__ void k_rmsnorm(const float* __restrict__ x, const float* __restrict__ w,
                          float* __restrict__ out) {
    int r = blockIdx.x;
    int tid = threadIdx.x;
    __shared__ float red[256];
    float s = 0.f;
    for (int c = tid; c < DM; c += 256) {
        float v = x[r * DM + c];
        s += v * v;
    }
    red[tid] = s;
    __syncthreads();
    for (int o = 128; o > 0; o >>= 1) {
        if (tid < o) red[tid] += red[tid + o];
        __syncthreads();
    }
    float scale = rsqrtf(red[0] / DM + 1e-5f);
    for (int c = tid; c < DM; c += 256) out[r * DM + c] = x[r * DM + c] * scale * w[c];
}

// ---------------- scalar fp32 GEMM (ro2) ----------------
template <int ACT>
__global__ void k_gemm(const float* __restrict__ A, const float* __restrict__ B,
                       float* __restrict__ C, const float* __restrict__ bias,
                       int N, int lda, int ldb, int ldc, int kcount) {
    __shared__ float As[16][68];
    __shared__ float Bs[16][68];
    int tid = threadIdx.x;
    int bm = blockIdx.y * 64, bn = blockIdx.x * 64;

    float acc[4][4] = {};
    int a_r = tid >> 2, a_k = (tid & 3) * 4;
    int ty = tid >> 4, tx = tid & 15;

    for (int k0 = 0; k0 < kcount; k0 += 16) {
        float4 av = *(const float4*)(A + (size_t)(bm + a_r) * lda + k0 + a_k);
        As[a_k + 0][a_r] = av.x;
        As[a_k + 1][a_r] = av.y;
        As[a_k + 2][a_r] = av.z;
        As[a_k + 3][a_r] = av.w;
        int b_r = tid >> 4, b_c = (tid & 15) * 4;
        float4 bv = *(const float4*)(B + (size_t)(k0 + b_r) * ldb + bn + b_c);
        *(float4*)&Bs[b_r][b_c] = bv;
        __syncthreads();
#pragma unroll
        for (int kk = 0; kk < 16; kk++) {
            float4 a = *(const float4*)&As[kk][ty * 4];
            float4 b = *(const float4*)&Bs[kk][tx * 4];
            float ar[4] = {a.x, a.y, a.z, a.w};
            float br[4] = {b.x, b.y, b.z, b.w};
#pragma unroll
            for (int i = 0; i < 4; i++)
#pragma unroll
                for (int j = 0; j < 4; j++) acc[i][j] = fmaf(ar[i], br[j], acc[i][j]);
        }
        __syncthreads();
    }
#pragma unroll
    for (int i = 0; i < 4; i++) {
        int m = bm + ty * 4 + i;
#pragma unroll
        for (int j = 0; j < 4; j++) {
            int n = bn + tx * 4 + j;
            float v = acc[i][j] + bias[n];
            if (ACT == 1) v = fmaxf(v, 0.f);
            C[(size_t)m * ldc + n] = v;
        }
    }
}

// ---------------- tensor-core GEMM core: split-bf16 3-pass, 128x64, BK=64 ---
__device__ __forceinline__ uint32_t smem_u32(const void* p) {
    uint32_t a;
    asm("{ .reg .u64 t; cvta.to.shared.u64 t, %1; cvt.u32.u64 %0, t; }" : "=r"(a) : "l"(p));
    return a;
}
__device__ __forceinline__ void mma_bf16(float* c, const uint32_t* a, const uint32_t* b) {
    asm volatile(
        "mma.sync.aligned.m16n8k16.row.col.f32.bf16.bf16.f32 "
        "{%0,%1,%2,%3}, {%4,%5,%6,%7}, {%8,%9}, {%0,%1,%2,%3};\n"
        : "+f"(c[0]), "+f"(c[1]), "+f"(c[2]), "+f"(c[3])
        : "r"(a[0]), "r"(a[1]), "r"(a[2]), "r"(a[3]), "r"(b[0]), "r"(b[1]));
}
__device__ __forceinline__ void ldsm4(uint32_t* r, uint32_t addr) {
    asm volatile("ldmatrix.sync.aligned.m8n8.x4.shared.b16 {%0,%1,%2,%3}, [%4];"
                 : "=r"(r[0]), "=r"(r[1]), "=r"(r[2]), "=r"(r[3]) : "r"(addr));
}

#define PAD 72
#define SM_MMA ((128 * PAD * 2 + 64 * PAD * 2) * 2)   // 55296 bytes

template <bool BT, bool FEAT, int MODE, bool NGUARD, bool HASBIAS>
__device__ __forceinline__ void gemm_core(
    char* sm, const float* __restrict__ A, const float* __restrict__ B,
    float* __restrict__ C, const float* __restrict__ bias,
    int N, int lda, int ldb, int ldc, int bm, int bn, int kbeg, int kcount) {
    __nv_bfloat16 (*Ah)[PAD] = (__nv_bfloat16(*)[PAD])(sm);
    __nv_bfloat16 (*Al)[PAD] = (__nv_bfloat16(*)[PAD])(sm + 128 * PAD * 2);
    __nv_bfloat16 (*Bh)[PAD] = (__nv_bfloat16(*)[PAD])(sm + 2 * 128 * PAD * 2);
    __nv_bfloat16 (*Bl)[PAD] = (__nv_bfloat16(*)[PAD])(sm + 2 * 128 * PAD * 2 + 64 * PAD * 2);

    const int tid = threadIdx.x;
    const int lane = tid & 31, warp = tid >> 5;
    const int wm = warp & 3, wn = warp >> 2;
    const int qrow = lane >> 2, qcol = (lane & 3) * 2;

    const float* Ap;
    int alda = lda;
    if (FEAT) {
        int layer = kbeg / DIDS;
        Ap = A + (size_t)layer * HID_LAYER_STRIDE + (kbeg % DIDS);
        alda = DIDS;
    } else {
        Ap = A + kbeg;
    }
    const float* Bp = BT ? (B + kbeg) : (B + (size_t)kbeg * ldb);

    float acc[2][4][4] = {};
    const int a_row = (lane & 15);
    const int a_koff = ((lane >> 4) & 1) * 8;
    const int b_rowsel = (lane & 7) + ((lane >> 4) & 1) * 8;
    const int b_koff = ((lane >> 3) & 1) * 8;

    for (int k0 = 0; k0 < kcount; k0 += 64) {
        // ---- stage A: 128x64 fp32 -> hi/lo bf16 ----
#pragma unroll
        for (int i = 0; i < 8; i++) {
            int id = tid + i * 256;
            int r = id >> 4, kq = (id & 15) * 4;
            float4 v = *(const float4*)(Ap + (size_t)(bm + r) * alda + k0 + kq);
            __nv_bfloat16 h0 = __float2bfloat16(v.x), h1 = __float2bfloat16(v.y);
            __nv_bfloat16 h2 = __float2bfloat16(v.z), h3 = __float2bfloat16(v.w);
            *(__nv_bfloat162*)&Ah[r][kq] = __halves2bfloat162(h0, h1);
            *(__nv_bfloat162*)&Ah[r][kq + 2] = __halves2bfloat162(h2, h3);
            *(__nv_bfloat162*)&Al[r][kq] = __halves2bfloat162(
                __float2bfloat16(v.x - __bfloat162float(h0)),
                __float2bfloat16(v.y - __bfloat162float(h1)));
            *(__nv_bfloat162*)&Al[r][kq + 2] = __halves2bfloat162(
                __float2bfloat16(v.z - __bfloat162float(h2)),
                __float2bfloat16(v.w - __bfloat162float(h3)));
        }
        // ---- stage B: 64x64 ----
        if (BT) {
#pragma unroll
            for (int i = 0; i < 4; i++) {
                int id = tid + i * 256;
                int nr = id >> 4, kq = (id & 15) * 4;
                float4 v = make_float4(0.f, 0.f, 0.f, 0.f);
                if (!NGUARD || (bn + nr) < N)
                    v = *(const float4*)(Bp + (size_t)(bn + nr) * ldb + k0 + kq);
                __nv_bfloat16 h0 = __float2bfloat16(v.x), h1 = __float2bfloat16(v.y);
                __nv_bfloat16 h2 = __float2bfloat16(v.z), h3 = __float2bfloat16(v.w);
                *(__nv_bfloat162*)&Bh[nr][kq] = __halves2bfloat162(h0, h1);
                *(__nv_bfloat162*)&Bh[nr][kq + 2] = __halves2bfloat162(h2, h3);
                *(__nv_bfloat162*)&Bl[nr][kq] = __halves2bfloat162(
                    __float2bfloat16(v.x - __bfloat162float(h0)),
                    __float2bfloat16(v.y - __bfloat162float(h1)));
                *(__nv_bfloat162*)&Bl[nr][kq + 2] = __halves2bfloat162(
                    __float2bfloat16(v.z - __bfloat162float(h2)),
                    __float2bfloat16(v.w - __bfloat162float(h3)));
            }
        } else {
#pragma unroll
            for (int i = 0; i < 4; i++) {
                int id = tid + i * 256;
                int kr = id >> 4, nq = (id & 15) * 4;
                float fv[4];
                if (!NGUARD || (bn + nq + 3) < N) {
                    float4 v = *(const float4*)(Bp + (size_t)(k0 + kr) * ldb + bn + nq);
                    fv[0] = v.x; fv[1] = v.y; fv[2] = v.z; fv[3] = v.w;
                } else {
#pragma unroll
                    for (int j = 0; j < 4; j++)
                        fv[j] = (bn + nq + j) < N ? Bp[(size_t)(k0 + kr) * ldb + bn + nq + j] : 0.f;
                }
#pragma unroll
                for (int j = 0; j < 4; j++) {
                    __nv_bfloat16 h = __float2bfloat16(fv[j]);
                    Bh[nq + j][kr] = h;
                    Bl[nq + j][kr] = __float2bfloat16(fv[j] - __bfloat162float(h));
                }
            }
        }
        __syncthreads();
        // ---- compute: 4 k16 steps via ldmatrix ----
#pragma unroll
        for (int ks = 0; ks < 64; ks += 16) {
            uint32_t ah[2][4], al[2][4], bh[2][4], bl[2][4];
#pragma unroll
            for (int mt = 0; mt < 2; mt++) {
                int r0 = wm * 32 + mt * 16 + a_row;
                ldsm4(ah[mt], smem_u32(&Ah[r0][ks + a_koff]));
                ldsm4(al[mt], smem_u32(&Al[r0][ks + a_koff]));
            }
#pragma unroll
            for (int np = 0; np < 2; np++) {
                int n0 = wn * 32 + np * 16 + b_rowsel;
                ldsm4(bh[np], smem_u32(&Bh[n0][ks + b_koff]));
                ldsm4(bl[np], smem_u32(&Bl[n0][ks + b_koff]));
            }
#pragma unroll
            for (int mt = 0; mt < 2; mt++)
#pragma unroll
                for (int np = 0; np < 2; np++)
#pragma unroll
                    for (int j = 0; j < 2; j++) {
                        float* c = acc[mt][np * 2 + j];
                        mma_bf16(c, ah[mt], bh[np] + j * 2);
                        mma_bf16(c, al[mt], bh[np] + j * 2);
                        mma_bf16(c, ah[mt], bl[np] + j * 2);
                    }
        }
        __syncthreads();
    }

    // ---- epilogue ----
#pragma unroll
    for (int mt = 0; mt < 2; mt++)
#pragma unroll
        for (int i = 0; i < 2; i++) {
            int m = bm + wm * 32 + mt * 16 + qrow + i * 8;
#pragma unroll
            for (int nt = 0; nt < 4; nt++)
#pragma unroll
                for (int j = 0; j < 2; j++) {
                    int n = bn + wn * 32 + nt * 8 + qcol + j;
                    if (NGUARD && n >= N) continue;
                    float v = acc[mt][nt][i * 2 + j];
                    if (HASBIAS) v += bias[n];
                    size_t idx = (size_t)m * ldc + n;
                    if (MODE == 0) C[idx] = v;
                    else if (MODE == 1) C[idx] += v;
                    else atomicAdd(&C[idx], v);
                }
        }
}

template <bool BT, bool FEAT, int MODE, bool NGUARD, bool HASBIAS>
__global__ void __launch_bounds__(256, 2)
k_mma(const float* __restrict__ A, const float* __restrict__ B, float* __restrict__ C,
      const float* __restrict__ bias, int N, int lda, int ldb, int ldc, int kcount) {
    extern __shared__ char sm[];
    gemm_core<BT, FEAT, MODE, NGUARD, HASBIAS>(
        sm, A, B, C, bias, N, lda, ldb, ldc,
        blockIdx.y * 128, blockIdx.x * 64, blockIdx.z * kcount, kcount);
}

// ---- dual kernel: lm-head tiles (bx < lmX) + ro1 split-K tiles (bx >= lmX) --
#define RO1_ZSPLIT 32
#define RO1_KC ((NLY * DIDS) / RO1_ZSPLIT)   // 3072
__global__ void __launch_bounds__(256, 2)
k_dual(const float* __restrict__ xn, const float* __restrict__ embed,
       float* __restrict__ out_main, const float* __restrict__ hid,
       const float* __restrict__ row1, float* __restrict__ h1, int lmX) {
    extern __shared__ char sm[];
    int bx = blockIdx.x;
    int bm = blockIdx.y * 128;
    if (bx < lmX) {
        // lm head: C[256,V] = xn @ embed^T
        gemm_core<true, false, 0, true, false>(
            sm, xn, embed, out_main, nullptr, V, DM, DM, V, bm, bx * 64, 0, DM);
    } else {
        // ro1 split-K chunk
        int q = bx - lmX;
        int zz = q >> 3, xx = q & 7;
        gemm_core<false, true, 2, false, false>(
            sm, hid, row1, h1, nullptr, ROH, 0, ROH, ROH, bm, xx * 64,
            zz * RO1_KC, RO1_KC);
    }
}

// ---------------- fused conv+silu, x_proj, dt+softplus ----------------
__global__ void k_cxd(const float* __restrict__ cw, const float* __restrict__ cb,
                      const float* __restrict__ xp, const float* __restrict__ dtw,
                      const float* __restrict__ dtb) {
    int r = blockIdx.x;
    int b = r / LL, t = r % LL;
    int tid = threadIdx.x;
    __shared__ float sxc[DI];
    __shared__ float part[3][80];
    __shared__ float sdbc[80];

    for (int d = tid; d < DI; d += 256) {
        float acc = cb[d];
#pragma unroll
        for (int k = 0; k < DC; k++) {
            int tt = t + k - (DC - 1);
            if (tt >= 0)
                acc = fmaf(cw[d * DC + k], g_xz[(size_t)(b * LL + tt) * (2 * DI) + d], acc);
        }
        acc = acc / (1.f + __expf(-acc));
        sxc[d] = acc;
        g_xconv[r * DI + d] = acc;
    }
    __syncthreads();

    if (tid < 240) {
        int n = tid % 80, ks = tid / 80;
        float acc = 0.f;
        int k0 = ks * 512;
#pragma unroll 8
        for (int k = 0; k < 512; k++) acc = fmaf(sxc[k0 + k], xp[(size_t)(k0 + k) * 80 + n], acc);
        part[ks][n] = acc;
    }
    __syncthreads();
    if (tid < 80) {
        float v = part[0][tid] + part[1][tid] + part[2][tid];
        sdbc[tid] = v;
        g_dbc[r * 80 + tid] = v;
    }
    __syncthreads();

    for (int d = tid; d < DI; d += 256) {
        float a = dtb[d];
#pragma unroll
        for (int k = 0; k < DTR; k++) a = fmaf(sdbc[k], dtw[(size_t)k * DI + d], a);
        g_delta[r * DI + d] = (a > 20.f) ? a : log1pf(__expf(a));
    }
}

// ---------------- scan + fused gate ----------------
__global__ void k_scan(const float* __restrict__ A_log_l, float* __restrict__ hidden,
                       const float* __restrict__ Dp, int layer) {
    int tid = blockIdx.x * blockDim.x + threadIdx.x;  // 49152
    int n = tid & 15;
    int d = (tid >> 4) % DI;
    int b = tid / (DI * DS);
    float Adn = -__expf(A_log_l[d * DS + n]);
    float Dd = Dp[d];
    float h = 0.f;
    float* hbase = hidden + (size_t)layer * HID_LAYER_STRIDE;
    for (int t = 0; t < LL; t++) {
        int row = b * LL + t;
        float del = g_delta[row * DI + d];
        float u = g_xconv[row * DI + d];
        float Bn = g_dbc[row * 80 + DTR + n];
        float Cn = g_dbc[row * 80 + DTR + DS + n];
        float dA = __expf(del * Adn);
        h = fmaf(dA, h, del * Bn * u);
        hbase[(size_t)row * DIDS + d * DS + n] = h;
        float p = h * Cn;
        p += __shfl_xor_sync(0xffffffffu, p, 8, 16);
        p += __shfl_xor_sync(0xffffffffu, p, 4, 16);
        p += __shfl_xor_sync(0xffffffffu, p, 2, 16);
        p += __shfl_xor_sync(0xffffffffu, p, 1, 16);
        if (n == 0) {
            float z = g_xz[(size_t)row * (2 * DI) + DI + d];
            float sz = z / (1.f + __expf(-z));
            g_y[row * DI + d] = (p + Dd * u) * sz;
        }
    }
}

__global__ void k_zero(float* __restrict__ p, int nelem) {
    int i = blockIdx.x * blockDim.x + threadIdx.x;
    if (i < nelem) p[i] = 0.f;
}

__global__ void k_bias_relu(float* __restrict__ p, const float* __restrict__ b, int cols,
                            int nelem) {
    int i = blockIdx.x * blockDim.x + threadIdx.x;
    if (i < nelem) {
        float v = p[i] + b[i % cols];
        p[i] = fmaxf(v, 0.f);
    }
}

// ---------------- launch ----------------
extern "C" void kernel_launch(void* const* d_in, const int* in_sizes, int n_in,
                              void* d_out, int out_size) {
    const int* ids = (const int*)d_in[0];
    const float* embed = (const float*)d_in[1];
    const float* norm_f = (const float*)d_in[2];
    const float* norm_w = (const float*)d_in[3];
    const float* in_proj = (const float*)d_in[4];
    const float* conv_w = (const float*)d_in[5];
    const float* conv_b = (const float*)d_in[6];
    const float* x_proj = (const float*)d_in[7];
    const float* dt_w = (const float*)d_in[8];
    const float* dt_b = (const float*)d_in[9];
    const float* A_log = (const float*)d_in[10];
    const float* Dp = (const float*)d_in[11];
    const float* out_proj = (const float*)d_in[12];
    const float* ro_w1 = (const float*)d_in[13];
    const float* ro_b1 = (const float*)d_in[14];
    const float* ro_w2 = (const float*)d_in[15];
    const float* ro_b2 = (const float*)d_in[16];
    const float* ro_w3 = (const float*)d_in[17];
    const float* ro_b3 = (const float*)d_in[18];
    (void)in_sizes; (void)n_in; (void)out_size;

    float* out = (float*)d_out;
    float* out_main = out;                            // (B,L,V)
    float* out_ro = out + (size_t)BL * V;             // (B,L,V)
    float* out_hid = out + (size_t)2 * BL * V;        // (NL,B,L,DI,DS)

    float *x, *xn, *xz, *y, *h1, *h2;
    cudaGetSymbolAddress((void**)&x, g_x);
    cudaGetSymbolAddress((void**)&xn, g_xn);
    cudaGetSymbolAddress((void**)&xz, g_xz);
    cudaGetSymbolAddress((void**)&y, g_y);
    cudaGetSymbolAddress((void**)&h1, g_h1);
    cudaGetSymbolAddress((void**)&h2, g_h2);

    auto kA = k_mma<false, false, 2, false, false>;  // NN atomic (in_proj, out_proj)
    auto kD = k_mma<false, false, 0, true,  true>;   // ro3 + bias
    cudaFuncSetAttribute(kA, cudaFuncAttributeMaxDynamicSharedMemorySize, SM_MMA);
    cudaFuncSetAttribute(kD, cudaFuncAttributeMaxDynamicSharedMemorySize, SM_MMA);
    cudaFuncSetAttribute(k_dual, cudaFuncAttributeMaxDynamicSharedMemorySize, SM_MMA);

    k_embed<<<(BL * DM + 255) / 256, 256>>>(ids, embed);
    // hoist h1 zero out of the tail
    k_zero<<<(BL * ROH + 255) / 256, 256>>>(h1, BL * ROH);

    for (int l = 0; l < NLY; l++) {
        k_rmsnorm<<<BL, 256>>>(x, norm_w + (size_t)l * DM, xn);

        // xz = xn @ in_proj[l]  split-K z=2 -> 192 CTAs
        k_zero<<<(BL * 2 * DI + 255) / 256, 256>>>(xz, BL * 2 * DI);
        kA<<<dim3(2 * DI / 64, BL / 128, 2), 256, SM_MMA>>>(
            xn, in_proj + (size_t)l * DM * 2 * DI, xz, nullptr, 2 * DI, DM, 2 * DI,
            2 * DI, DM / 2);

        // fused conv+silu, x_proj, dt+softplus
        k_cxd<<<BL, 256>>>(conv_w + (size_t)l * DI * DC, conv_b + (size_t)l * DI,
                           x_proj + (size_t)l * DI * 80, dt_w + (size_t)l * DTR * DI,
                           dt_b + (size_t)l * DI);

        // scan + fused gate
        k_scan<<<(BB * DI * DS) / 256, 256>>>(A_log + (size_t)l * DIDS, out_hid,
                                              Dp + (size_t)l * DI, l);

        // x += y @ out_proj[l]  split-K z=6 -> 144 CTAs
        kA<<<dim3(DM / 64, BL / 128, 6), 256, SM_MMA>>>(
            y, out_proj + (size_t)l * DI * DM, x, nullptr, DM, DI, DM, DM, DI / 6);
    }

    // final norm, then fused (lm head || readout-1 split-K) in one launch
    k_rmsnorm<<<BL, 256>>>(x, norm_f, xn);
    const int lmX = (V + 63) / 64;                    // 786
    k_dual<<<dim3(lmX + 8 * RO1_ZSPLIT, BL / 128, 1), 256, SM_MMA>>>(
        xn, embed, out_main, out_hid, ro_w1, h1, lmX);

    k_bias_relu<<<(BL * ROH + 255) / 256, 256>>>(h1, ro_b1, ROH, BL * ROH);

    // readout layer 2 (scalar, tiny)
    k_gemm<1><<<dim3(256 / 64, BL / 64), 256>>>(h1, ro_w2, h2, ro_b2, 256, ROH, 256, 256, ROH);

    // readout logits = h2 @ ro_w3 + b3
    kD<<<dim3((V + 63) / 64, BL / 128, 1), 256, SM_MMA>>>(
        h2, ro_w3, out_ro, ro_b3, V, 256, V, V, 256);
}